// round 17
// baseline (speedup 1.0000x reference)
#include <cuda_runtime.h>
#include <cuda_bf16.h>
#include <math.h>
#include <cstdint>

// Problem shape (fixed by the dataset)
#define Q 256
#define I 2048
#define D 256

#define SE_INV_TEMP 5.0f     // 1/0.2
#define BN_EPS 1e-5f

// ---------------- device scratch (no allocs allowed) ----------------
__device__ __align__(16) __nv_bfloat16 g_Wb[Q * D];    // u_hat * a
__device__ __align__(16) __nv_bfloat16 g_A2b[Q * D];   // a*a
__device__ __align__(16) __nv_bfloat16 g_C2b[Q * D];   // 2*a*c
__device__ __align__(16) __nv_bfloat16 g_Yb[I * D];    // normalized gallery y
__device__ __align__(16) __nv_bfloat16 g_Y2b[I * D];   // y*y
__device__ float g_b1[Q];                              // <u_hat, c>
__device__ float g_cc;                                 // ||c||^2

// ---------------- PTX helpers (sm_80-era ops only: legal on compute_103) ----
__device__ __forceinline__ void cp16(uint32_t dst, const void* src) {
    asm volatile("cp.async.ca.shared.global [%0], [%1], 16;"
                 :: "r"(dst), "l"(src));
}
#define CP_COMMIT() asm volatile("cp.async.commit_group;" ::: "memory")
#define CP_WAIT(n)  asm volatile("cp.async.wait_group %0;" :: "n"(n) : "memory")

__device__ __forceinline__ void ldmx4(uint32_t* r, uint32_t a) {
    asm volatile("ldmatrix.sync.aligned.m8n8.x4.shared.b16 {%0,%1,%2,%3}, [%4];"
                 : "=r"(r[0]), "=r"(r[1]), "=r"(r[2]), "=r"(r[3]) : "r"(a));
}

__device__ __forceinline__ void mma16816(float* d, const uint32_t* a,
                                         const uint32_t* b) {
    asm volatile(
        "mma.sync.aligned.m16n8k16.row.col.f32.bf16.bf16.f32 "
        "{%0,%1,%2,%3}, {%4,%5,%6,%7}, {%8,%9}, {%0,%1,%2,%3};"
        : "+f"(d[0]), "+f"(d[1]), "+f"(d[2]), "+f"(d[3])
        : "r"(a[0]), "r"(a[1]), "r"(a[2]), "r"(a[3]), "r"(b[0]), "r"(b[1]));
}

// per-group named barrier (group g: threads g*256..g*256+255)
__device__ __forceinline__ void group_bar(int id) {
    asm volatile("bar.sync %0, 256;" :: "r"(id) : "memory");
}

// ---------------- warp reduction ----------------
__device__ __forceinline__ float wsum(float v) {
#pragma unroll
    for (int o = 16; o > 0; o >>= 1) v += __shfl_xor_sync(0xffffffffu, v, o);
    return v;
}

__device__ __forceinline__ uint4 pack8_bf16(const float* v) {
    __nv_bfloat162 a = __floats2bfloat162_rn(v[0], v[1]);
    __nv_bfloat162 b = __floats2bfloat162_rn(v[2], v[3]);
    __nv_bfloat162 c = __floats2bfloat162_rn(v[4], v[5]);
    __nv_bfloat162 d = __floats2bfloat162_rn(v[6], v[7]);
    uint4 r;
    r.x = *(unsigned*)&a; r.y = *(unsigned*)&b;
    r.z = *(unsigned*)&c; r.w = *(unsigned*)&d;
    return r;
}

// ---------------- fused preprocess: warp per row ----------------
// blocks 0..31: queries (8 per block). blocks 32..287: gallery rows (8 per block).
__global__ __launch_bounds__(256) void prep_kernel(
    const float* __restrict__ xq_in, const float* __restrict__ yq_in,
    const float* __restrict__ yg_in,
    const float* __restrict__ gamma, const float* __restrict__ beta,
    const float* __restrict__ mean,  const float* __restrict__ var) {
    const int lane = threadIdx.x & 31;
    const int warp = threadIdx.x >> 5;
    const int b = blockIdx.x;
    const int d0 = lane << 3;     // 8 elements per lane

    if (b < 32) {
        const int q = (b << 3) + warp;
        float x[8], y[8], a[8], c[8];
#pragma unroll
        for (int j = 0; j < 2; ++j) {
            float4 v = *(const float4*)(xq_in + (q << 8) + d0 + 4 * j);
            x[4*j+0]=v.x; x[4*j+1]=v.y; x[4*j+2]=v.z; x[4*j+3]=v.w;
            float4 w = *(const float4*)(yq_in + (q << 8) + d0 + 4 * j);
            y[4*j+0]=w.x; y[4*j+1]=w.y; y[4*j+2]=w.z; y[4*j+3]=w.w;
        }
        float gm[8], bt[8], mn[8], vr[8];
#pragma unroll
        for (int j = 0; j < 2; ++j) {
            float4 g4 = *(const float4*)(gamma + d0 + 4 * j);
            gm[4*j+0]=g4.x; gm[4*j+1]=g4.y; gm[4*j+2]=g4.z; gm[4*j+3]=g4.w;
            float4 b4 = *(const float4*)(beta + d0 + 4 * j);
            bt[4*j+0]=b4.x; bt[4*j+1]=b4.y; bt[4*j+2]=b4.z; bt[4*j+3]=b4.w;
            float4 m4 = *(const float4*)(mean + d0 + 4 * j);
            mn[4*j+0]=m4.x; mn[4*j+1]=m4.y; mn[4*j+2]=m4.z; mn[4*j+3]=m4.w;
            float4 v4 = *(const float4*)(var + d0 + 4 * j);
            vr[4*j+0]=v4.x; vr[4*j+1]=v4.y; vr[4*j+2]=v4.z; vr[4*j+3]=v4.w;
        }

        float sx = 0.f, sy = 0.f;
#pragma unroll
        for (int k = 0; k < 8; ++k) { sx = fmaf(x[k], x[k], sx); sy = fmaf(y[k], y[k], sy); }
        const float invx = 1.f / fmaxf(sqrtf(wsum(sx)), 1e-12f);
        const float invy = 1.f / fmaxf(sqrtf(wsum(sy)), 1e-12f);

        float fq[8];
        float sf = 0.f;
#pragma unroll
        for (int k = 0; k < 8; ++k) {
            float xn = x[k] * invx;
            float gate = 1.f / (1.f + __expf(-xn * SE_INV_TEMP));
            float istd = gm[k] * rsqrtf(vr[k] + BN_EPS);
            c[k] = bt[k] - mn[k] * istd;
            a[k] = gate * istd;
            float yn = y[k] * invy;
            fq[k] = fmaf(yn, a[k], c[k]);
            sf = fmaf(fq[k], fq[k], sf);
        }
        const float invf = 1.f / fmaxf(sqrtf(wsum(sf)), 1e-12f);

        float b1p = 0.f;
        float w_[8], a2_[8], c2_[8];
#pragma unroll
        for (int k = 0; k < 8; ++k) {
            float u = fq[k] * invf;
            w_[k]  = u * a[k];
            a2_[k] = a[k] * a[k];
            c2_[k] = 2.f * a[k] * c[k];
            b1p = fmaf(u, c[k], b1p);
        }
        *(uint4*)(g_Wb  + (q << 8) + d0) = pack8_bf16(w_);
        *(uint4*)(g_A2b + (q << 8) + d0) = pack8_bf16(a2_);
        *(uint4*)(g_C2b + (q << 8) + d0) = pack8_bf16(c2_);

        float b1 = wsum(b1p);
        if (lane == 0) g_b1[q] = b1;
        if (q == 0) {
            float ccp = 0.f;
#pragma unroll
            for (int k = 0; k < 8; ++k) ccp = fmaf(c[k], c[k], ccp);
            float cc = wsum(ccp);
            if (lane == 0) g_cc = cc;
        }
    } else {
        const int i = ((b - 32) << 3) + warp;
        float v[8];
        float s = 0.f;
#pragma unroll
        for (int j = 0; j < 2; ++j) {
            float4 v4 = *(const float4*)(yg_in + (i << 8) + d0 + 4 * j);
            v[4*j+0]=v4.x; v[4*j+1]=v4.y; v[4*j+2]=v4.z; v[4*j+3]=v4.w;
        }
#pragma unroll
        for (int k = 0; k < 8; ++k) s = fmaf(v[k], v[k], s);
        const float inv = 1.f / fmaxf(sqrtf(wsum(s)), 1e-12f);
        float yn[8], y2[8];
#pragma unroll
        for (int k = 0; k < 8; ++k) { yn[k] = v[k] * inv; y2[k] = yn[k] * yn[k]; }
        *(uint4*)(g_Yb  + (i << 8) + d0) = pack8_bf16(yn);
        *(uint4*)(g_Y2b + (i << 8) + d0) = pack8_bf16(y2);
    }
}

// ---------------- main: HMMA split-K triple-GEMM, software-pipelined ---------
// CTA tile 64q x 64i, grid 32x4 = 128 CTAs (one wave), 512 threads (16 warps).
// Split-K: group 0 (warps 0-7) K[0,128), group 1 (warps 8-15) K[128,256).
// Warps tile 2m x 4n, warp tile 32q x 16i. Each group fills only its own two
// K-chunks via cp.async; per-group named barriers.
// Mainloop: explicit two-stage FRAGMENT pipeline (fr0/fr1) so LDSM latency is
// hidden under the MMA burst of the other stage (asm volatile blocks ptxas
// from doing this itself).
// Split-K merge: each group spills only its other-mt half; both groups merge
// and run the epilogue on their own mt half (2x epilogue parallelism).
// Row stride 144B: 16B-aligned (cp.async) and conflict-free for ldmatrix.
#define BK 64
#define NCH (D / BK)            // 4
#define SRL 144                 // row stride bytes
#define MATB (64 * SRL)         // 9216
#define BUFB (5 * MATB)         // 46080
#define SMEM_SCORE (NCH * BUFB) // 184320

__global__ __launch_bounds__(512) void score_kernel(float* __restrict__ out) {
    extern __shared__ __align__(16) char smem[];

    const int tid = threadIdx.x;
    const int wid = tid >> 5;
    const int lane = tid & 31;
    const int kh = wid >> 3;         // k-group 0/1
    const int wg = wid & 7;          // warp within group
    const int wm = wg & 1;
    const int wn = wg >> 1;
    const int qb = blockIdx.y << 6;
    const int ib = blockIdx.x << 6;

    const uint32_t sb0 = (uint32_t)__cvta_generic_to_shared(&smem[0]);

    // cp.async mapping: per chunk per matrix 512 16B-units, 2 per group-thread.
    const int tg = tid & 255;        // thread index within group
    const int u0 = tg, u1 = tg + 256;
    const int r0_ = u0 >> 3, c0_ = u0 & 7;
    const int r1_ = u1 >> 3, c1_ = u1 & 7;

#define LOAD_CHUNK(ch) do {                                                   \
        const int kc_ = (ch) * BK;                                            \
        const uint32_t db_ = sb0 + (ch) * BUFB;                               \
        const uint32_t dA_ = db_ + r0_ * SRL + c0_ * 16;                      \
        const uint32_t dB_ = db_ + r1_ * SRL + c1_ * 16;                      \
        const int sA_ = r0_ * D + kc_ + c0_ * 8;                              \
        const int sB_ = r1_ * D + kc_ + c1_ * 8;                              \
        cp16(dA_ + 0 * MATB, g_Wb  + qb * D + sA_);                           \
        cp16(dB_ + 0 * MATB, g_Wb  + qb * D + sB_);                           \
        cp16(dA_ + 1 * MATB, g_A2b + qb * D + sA_);                           \
        cp16(dB_ + 1 * MATB, g_A2b + qb * D + sB_);                           \
        cp16(dA_ + 2 * MATB, g_C2b + qb * D + sA_);                           \
        cp16(dB_ + 2 * MATB, g_C2b + qb * D + sB_);                           \
        cp16(dA_ + 3 * MATB, g_Yb  + ib * D + sA_);                           \
        cp16(dB_ + 3 * MATB, g_Yb  + ib * D + sB_);                           \
        cp16(dA_ + 4 * MATB, g_Y2b + ib * D + sA_);                           \
        cp16(dB_ + 4 * MATB, g_Y2b + ib * D + sB_);                           \
    } while (0)

    // each group loads only its own two chunks
    const int chA = 2 * kh, chB = 2 * kh + 1;
    LOAD_CHUNK(chA); CP_COMMIT();
    LOAD_CHUNK(chB); CP_COMMIT();

    // ldmatrix per-lane base addresses (chunk 0 offsets)
    const int lrow = ((lane >> 3) & 1) * 8 + (lane & 7);
    const int kb = ((lane >> 4) & 1) * 16;
    uint32_t adW[2], adA[2], adC[2];
#pragma unroll
    for (int mt = 0; mt < 2; ++mt) {
        const int r = wm * 32 + mt * 16 + lrow;
        adW[mt] = sb0 + 0 * MATB + r * SRL + kb;
        adA[mt] = sb0 + 1 * MATB + r * SRL + kb;
        adC[mt] = sb0 + 2 * MATB + r * SRL + kb;
    }
    const int rB = wn * 16 + lrow;
    const uint32_t adY  = sb0 + 3 * MATB + rB * SRL + kb;
    const uint32_t adY2 = sb0 + 4 * MATB + rB * SRL + kb;

    float num[2][2][4], den[2][2][4];
#pragma unroll
    for (int mt = 0; mt < 2; ++mt)
#pragma unroll
        for (int nt = 0; nt < 2; ++nt)
#pragma unroll
            for (int k = 0; k < 4; ++k) { num[mt][nt][k] = 0.f; den[mt][nt][k] = 0.f; }

    // fragment sets: [0]=w0 [1]=w1 [2]=a0 [3]=a1 [4]=c0 [5]=c1 [6]=y [7]=y2
    uint32_t fr0[8][4], fr1[8][4];

#define LDFRAG(F, ko) do {                                                    \
        ldmx4((F)[0], adW[0] + (ko)); ldmx4((F)[1], adW[1] + (ko));           \
        ldmx4((F)[2], adA[0] + (ko)); ldmx4((F)[3], adA[1] + (ko));           \
        ldmx4((F)[4], adC[0] + (ko)); ldmx4((F)[5], adC[1] + (ko));           \
        ldmx4((F)[6], adY  + (ko));   ldmx4((F)[7], adY2 + (ko));             \
    } while (0)

#define MMAFRAG(F) do {                                                       \
        uint32_t Y0[2] = {(F)[6][0], (F)[6][2]}, Y1[2] = {(F)[6][1], (F)[6][3]};\
        uint32_t Z0[2] = {(F)[7][0], (F)[7][2]}, Z1[2] = {(F)[7][1], (F)[7][3]};\
        mma16816(num[0][0], (F)[0], Y0); mma16816(num[0][1], (F)[0], Y1);     \
        mma16816(num[1][0], (F)[1], Y0); mma16816(num[1][1], (F)[1], Y1);     \
        mma16816(den[0][0], (F)[2], Z0); mma16816(den[0][1], (F)[2], Z1);     \
        mma16816(den[1][0], (F)[3], Z0); mma16816(den[1][1], (F)[3], Z1);     \
        mma16816(den[0][0], (F)[4], Y0); mma16816(den[0][1], (F)[4], Y1);     \
        mma16816(den[1][0], (F)[5], Y0); mma16816(den[1][1], (F)[5], Y1);     \
    } while (0)

    // two-stage pipelined chunk: LDSM of step k+2 issued before MMA of step k+1
#define PIPE_CHUNK(boff) do {                                                 \
        LDFRAG(fr0, (boff));                                                  \
        LDFRAG(fr1, (boff) + 32);                                             \
        MMAFRAG(fr0);                                                         \
        LDFRAG(fr0, (boff) + 64);                                             \
        MMAFRAG(fr1);                                                         \
        LDFRAG(fr1, (boff) + 96);                                             \
        MMAFRAG(fr0);                                                         \
        MMAFRAG(fr1);                                                         \
    } while (0)

    CP_WAIT(1);
    group_bar(kh + 1);
    PIPE_CHUNK(chA * BUFB);
    CP_WAIT(0);
    group_bar(kh + 1);
    PIPE_CHUNK(chB * BUFB);

    // ---- split-K merge: each group spills its OTHER-mt half, merges its own,
    //      and runs the epilogue on mt == kh (both groups work) ----
    __syncthreads();
    float* mf = (float*)smem;                 // 32KB scratch (reuses buffers)
    const int t = wg * 32 + lane;             // 0..255 within group
    const int omt = 1 - kh;                   // half we hand to the other group
    {
        float* my = mf + kh * 4096;
#pragma unroll
        for (int nt = 0; nt < 2; ++nt)
#pragma unroll
            for (int k = 0; k < 4; ++k) {
                const int j = nt * 4 + k;
                my[j * 256 + t]       = num[omt][nt][k];
                my[(8 + j) * 256 + t] = den[omt][nt][k];
            }
    }
    __syncthreads();
    {
        const float* ot = mf + (1 - kh) * 4096;
#pragma unroll
        for (int nt = 0; nt < 2; ++nt)
#pragma unroll
            for (int k = 0; k < 4; ++k) {
                const int j = nt * 4 + k;
                num[kh][nt][k] += ot[j * 256 + t];
                den[kh][nt][k] += ot[(8 + j) * 256 + t];
            }
    }

    // epilogue: score = sigmoid( (num + b1[q]) * rsqrt(den + cc) ), rows mt==kh
    const float ccv = g_cc;
    {
        const int r0 = qb + wm * 32 + kh * 16 + (lane >> 2);
        const float b1a = g_b1[r0];
        const float b1b = g_b1[r0 + 8];
#pragma unroll
        for (int nt = 0; nt < 2; ++nt) {
            const int col = ib + wn * 16 + nt * 8 + ((lane & 3) << 1);
            const float* d = num[kh][nt];
            const float* e = den[kh][nt];
            float v0 = (d[0] + b1a) * rsqrtf(fmaxf(e[0] + ccv, 1e-24f));
            float v1 = (d[1] + b1a) * rsqrtf(fmaxf(e[1] + ccv, 1e-24f));
            float v2 = (d[2] + b1b) * rsqrtf(fmaxf(e[2] + ccv, 1e-24f));
            float v3 = (d[3] + b1b) * rsqrtf(fmaxf(e[3] + ccv, 1e-24f));
            float2 p0, p1;
            p0.x = 1.f / (1.f + __expf(-v0));
            p0.y = 1.f / (1.f + __expf(-v1));
            p1.x = 1.f / (1.f + __expf(-v2));
            p1.y = 1.f / (1.f + __expf(-v3));
            *(float2*)(out + (size_t)r0 * I + col) = p0;
            *(float2*)(out + (size_t)(r0 + 8) * I + col) = p1;
        }
    }
}

// ---------------- entry ----------------
extern "C" void kernel_launch(void* const* d_in, const int* in_sizes, int n_in,
                              void* d_out, int out_size) {
    const float* query_feats      = (const float*)d_in[0];
    const float* query_img_feats  = (const float*)d_in[1];
    const float* gallery_img_feats= (const float*)d_in[2];
    const float* bn_gamma         = (const float*)d_in[3];
    const float* bn_beta          = (const float*)d_in[4];
    const float* bn_mean          = (const float*)d_in[5];
    const float* bn_var           = (const float*)d_in[6];
    float* out = (float*)d_out;

    cudaFuncSetAttribute(score_kernel,
                         cudaFuncAttributeMaxDynamicSharedMemorySize, SMEM_SCORE);

    prep_kernel<<<288, 256>>>(query_feats, query_img_feats, gallery_img_feats,
                              bn_gamma, bn_beta, bn_mean, bn_var);
    score_kernel<<<dim3(I / 64, Q / 64), 512, SMEM_SCORE>>>(out);
}